// round 12
// baseline (speedup 1.0000x reference)
#include <cuda_runtime.h>
#include <cuda_bf16.h>
#include <math.h>
#include <stdint.h>

#define B_      32
#define CIN     128
#define COUT    128
#define HW      128
#define ZD      512
#define EPSV    1e-8f

// ---------------- device scratch ----------------
__device__ float g_mod[B_ * CIN];
__device__ float g_S[COUT * CIN];
__device__ float g_dscale[B_ * COUT];
__device__ unsigned int g_sxbits[B_];          // max|x| per batch (uint-compare)
__device__ float g_fs[B_ * COUT];              // s1x * s1w * dscale
// int8 weights (w*mod), 2 levels: [b][st=tap*2+ih][oc][64]
__device__ __align__(256) signed char g_w1[B_ * 18 * 128 * 64];
__device__ __align__(256) signed char g_w2[B_ * 18 * 128 * 64];
// int8 x (raw), 2 levels, NHWC: [b][y][x][ic]
__device__ __align__(256) signed char g_x1[(size_t)B_ * HW * HW * CIN];
__device__ __align__(256) signed char g_x2[(size_t)B_ * HW * HW * CIN];

// ---------------- helpers ----------------
__device__ __forceinline__ uint32_t smem_u32(const void* p) {
    uint32_t a;
    asm("{ .reg .u64 t; cvta.to.shared.u64 t, %1; cvt.u32.u64 %0, t; }" : "=r"(a) : "l"(p));
    return a;
}
__device__ __forceinline__ void cpasync16(uint32_t dst, const void* src, int sz) {
    asm volatile("cp.async.cg.shared.global [%0], [%1], 16, %2;"
        :: "r"(dst), "l"(src), "r"(sz) : "memory");
}
#define CP_COMMIT() asm volatile("cp.async.commit_group;" ::: "memory")
#define CP_WAIT1()  asm volatile("cp.async.wait_group 1;" ::: "memory")
#define CP_WAIT0()  asm volatile("cp.async.wait_group 0;" ::: "memory")

__device__ __forceinline__ void ldsm_x4(uint32_t a[4], uint32_t addr) {
    asm volatile("ldmatrix.sync.aligned.m8n8.x4.shared.b16 {%0,%1,%2,%3}, [%4];"
        : "=r"(a[0]), "=r"(a[1]), "=r"(a[2]), "=r"(a[3]) : "r"(addr));
}
__device__ __forceinline__ void imma(int d[4], const uint32_t a[4], const uint32_t b[2]) {
    asm volatile("mma.sync.aligned.m16n8k32.row.col.s32.s8.s8.s32 "
        "{%0,%1,%2,%3}, {%4,%5,%6,%7}, {%8,%9}, {%0,%1,%2,%3};"
        : "+r"(d[0]), "+r"(d[1]), "+r"(d[2]), "+r"(d[3])
        : "r"(a[0]), "r"(a[1]), "r"(a[2]), "r"(a[3]), "r"(b[0]), "r"(b[1]));
}
__device__ __forceinline__ float mishf(float v) {
    return v * tanhf(log1pf(expf(v)));
}

// ---------------- pre-kernels ----------------
__global__ void zmax_kernel() {
    if (threadIdx.x < B_) g_sxbits[threadIdx.x] = 0u;
}

__global__ void style_kernel(const float* __restrict__ z,
                             const float* __restrict__ Wsty,
                             const float* __restrict__ bsty) {
    int b = blockIdx.x, i = threadIdx.x;
    __shared__ float zs[ZD];
    for (int k = threadIdx.x; k < ZD; k += blockDim.x) zs[k] = z[b * ZD + k];
    __syncthreads();
    float s = bsty[i];
    const float* wr = Wsty + i * ZD;
    #pragma unroll 4
    for (int k = 0; k < ZD; k++) s += zs[k] * wr[k];
    g_mod[b * CIN + i] = s + 1.0f;
}

__global__ void ssum_kernel(const float* __restrict__ w) {
    int o = blockIdx.x, i = threadIdx.x;
    const float* p = w + (o * CIN + i) * 9;
    float s = 0.f;
    #pragma unroll
    for (int k = 0; k < 9; k++) s += p[k] * p[k];
    g_S[o * CIN + i] = s;
}

__global__ void dscale_kernel() {
    int b = blockIdx.x, o = threadIdx.x;
    const float* m = g_mod + b * CIN;
    const float* s = g_S + o * CIN;
    float acc = 0.f;
    #pragma unroll 4
    for (int i = 0; i < CIN; i++) { float mv = m[i]; acc += mv * mv * s[i]; }
    g_dscale[b * COUT + o] = rsqrtf(acc + EPSV);
}

// max|x| per batch
__global__ void xmax_kernel(const float* __restrict__ x) {
    int b   = blockIdx.x >> 3;
    int sub = blockIdx.x & 7;
    const float* base = x + (size_t)b * CIN * HW * HW + (size_t)sub * (CIN * HW * HW / 8);
    float m = 0.f;
    for (int i = threadIdx.x; i < CIN * HW * HW / 8; i += 256)
        m = fmaxf(m, fabsf(base[i]));
    // warp reduce
    #pragma unroll
    for (int o = 16; o; o >>= 1)
        m = fmaxf(m, __shfl_xor_sync(0xffffffffu, m, o));
    __shared__ float red[8];
    if ((threadIdx.x & 31) == 0) red[threadIdx.x >> 5] = m;
    __syncthreads();
    if (threadIdx.x == 0) {
        #pragma unroll
        for (int i = 1; i < 8; i++) m = fmaxf(m, red[i]);
        atomicMax(&g_sxbits[b], __float_as_uint(m));
    }
}

// w' = w*mod, per-(b,oc)-row two-level int8 quant; also g_fs
__global__ void wquant_kernel(const float* __restrict__ w) {
    int b  = blockIdx.x >> 7;
    int oc = blockIdx.x & 127;
    int ic = threadIdx.x;
    float m = g_mod[b * CIN + ic];
    float wv[9];
    const float* wr = w + (oc * CIN + ic) * 9;
    float mx = 0.f;
    #pragma unroll
    for (int k = 0; k < 9; k++) { wv[k] = wr[k] * m; mx = fmaxf(mx, fabsf(wv[k])); }
    __shared__ float red[128];
    red[ic] = mx;
    __syncthreads();
    #pragma unroll
    for (int o = 64; o; o >>= 1) {
        if (ic < o) red[ic] = fmaxf(red[ic], red[ic + o]);
        __syncthreads();
    }
    float rmax = fmaxf(red[0], 1e-30f);
    float s1 = rmax / 127.f, inv1 = 127.f / rmax;
    float s2 = s1 * 0.0078125f, inv2 = 1.f / s2;
    int ih = ic >> 6, j = ic & 63;
    #pragma unroll
    for (int k = 0; k < 9; k++) {
        float v  = wv[k];
        float q1 = rintf(v * inv1);
        q1 = fminf(fmaxf(q1, -127.f), 127.f);
        float r  = v - q1 * s1;
        float q2 = rintf(r * inv2);
        q2 = fminf(fmaxf(q2, -127.f), 127.f);
        size_t o = (((size_t)b * 18 + (k * 2 + ih)) * 128 + oc) * 64 + j;
        g_w1[o] = (signed char)(int)q1;
        g_w2[o] = (signed char)(int)q2;
    }
    if (ic == 0) {
        float sx = __uint_as_float(g_sxbits[b]) / 127.f;
        g_fs[b * COUT + oc] = s1 * sx * g_dscale[b * COUT + oc];
    }
}

// x raw -> two-level int8, NHWC transpose
__global__ void xquant_kernel(const float* __restrict__ x) {
    extern __shared__ float sm[];   // 128 * 133
    int b = blockIdx.x >> 7;
    int y = blockIdx.x & 127;
    #pragma unroll
    for (int i = 0; i < 16; i++) {
        int idx4 = i * 256 + threadIdx.x;
        int ic = idx4 >> 5;
        int x4 = (idx4 & 31) * 4;
        float4 v = *(const float4*)(x + (((size_t)(b * CIN + ic)) * HW + y) * HW + x4);
        float* d = sm + ic * 133 + x4;
        d[0] = v.x; d[1] = v.y; d[2] = v.z; d[3] = v.w;
    }
    __syncthreads();
    float sx  = __uint_as_float(g_sxbits[b]);
    float s1  = fmaxf(sx, 1e-30f) / 127.f;
    float inv1 = 1.f / s1;
    float s2  = s1 * 0.0078125f;
    float inv2 = 1.f / s2;
    int xc = threadIdx.x >> 1;
    int ih = threadIdx.x & 1;
    size_t o = (((size_t)(b * HW + y)) * HW + xc) * CIN + ih * 64;
    uint32_t* o1 = (uint32_t*)(g_x1 + o);
    uint32_t* o2 = (uint32_t*)(g_x2 + o);
    #pragma unroll
    for (int q = 0; q < 16; q++) {
        uint32_t p1 = 0, p2 = 0;
        #pragma unroll
        for (int j = 0; j < 4; j++) {
            float v  = sm[(ih * 64 + q * 4 + j) * 133 + xc];
            float q1 = rintf(v * inv1);
            q1 = fminf(fmaxf(q1, -127.f), 127.f);
            float r  = v - q1 * s1;
            float q2 = rintf(r * inv2);
            q2 = fminf(fmaxf(q2, -127.f), 127.f);
            p1 |= ((uint32_t)((int)q1 & 0xFF)) << (j * 8);
            p2 |= ((uint32_t)((int)q2 & 0xFF)) << (j * 8);
        }
        o1[q] = p1;
        o2[q] = p2;
    }
}

// ---------------- main conv: IMMA implicit GEMM ----------------
// CTA = (b, row y0). D[128 oc x 128 px], K = 18 stages of 64 (2 k32 each).
// smem rows: 64 int8 data at 80B pitch (16*5 -> conflict-free ldmatrix).
#define ROWP     80
#define TILE_SZ  (128 * ROWP)        // 10240
#define OFF_A1   0
#define OFF_A2   (TILE_SZ)
#define OFF_B1   (2 * TILE_SZ)
#define OFF_B2   (3 * TILE_SZ)
#define STAGE_B  (4 * TILE_SZ)       // 40960
#define SM_TOTAL (2 * STAGE_B)       // 81920

__global__ void __launch_bounds__(512, 1)
conv_mma_kernel(float* __restrict__ out) {
    extern __shared__ __align__(1024) unsigned char smem[];
    const uint32_t sb = smem_u32(smem);
    const int t   = threadIdx.x;
    const int wid = t >> 5;
    const int lid = t & 31;
    const int b   = blockIdx.x >> 7;
    const int y0  = blockIdx.x & 127;

    const int oc0 = (wid & 3) * 32;
    const int n0  = (wid >> 2) * 32;

    int d1[2][4][4], d2[2][4][4];
    #pragma unroll
    for (int mi = 0; mi < 2; mi++)
        #pragma unroll
        for (int ni = 0; ni < 4; ni++)
            #pragma unroll
            for (int j = 0; j < 4; j++) { d1[mi][ni][j] = 0; d2[mi][ni][j] = 0; }

    auto issue_stage = [&](int s, int buf) {
        const int tap = s >> 1;
        const int ih  = s & 1;
        const int ky  = tap / 3;
        const int kx  = tap - ky * 3;
        const uint32_t bb = sb + (uint32_t)buf * STAGE_B;
        // A: 2 levels x 128 rows x 4 granules = 1024 cp16
        #pragma unroll
        for (int i = 0; i < 2; i++) {
            int idx = i * 512 + t;
            int lvl = idx >> 9;
            int r   = idx & 511;
            int oc  = r >> 2, g = r & 3;
            const signed char* src = (lvl ? g_w2 : g_w1)
                + (((size_t)b * 18 + s) * 128 + oc) * 64 + g * 16;
            cpasync16(bb + (lvl ? OFF_A2 : OFF_A1) + oc * ROWP + g * 16, src, 16);
        }
        // B: 2 levels x 128 px x 4 granules, halo zfill
        const int yi = y0 + ky - 1;
        const bool yok = (unsigned)yi < (unsigned)HW;
        #pragma unroll
        for (int i = 0; i < 2; i++) {
            int idx = i * 512 + t;
            int lvl = idx >> 9;
            int r   = idx & 511;
            int px  = r >> 2, g = r & 3;
            int xi  = px + kx - 1;
            bool ok = yok && (unsigned)xi < (unsigned)HW;
            const signed char* src = (lvl ? g_x2 : g_x1)
                + (((size_t)(b * HW + (ok ? yi : 0))) * HW + (ok ? xi : 0)) * CIN + ih * 64 + g * 16;
            cpasync16(bb + (lvl ? OFF_B2 : OFF_B1) + px * ROWP + g * 16, src, ok ? 16 : 0);
        }
    };

    issue_stage(0, 0);
    CP_COMMIT();

    for (int s = 0; s < 18; s++) {
        const int buf = s & 1;
        if (s + 1 < 18) {
            issue_stage(s + 1, buf ^ 1);
            CP_COMMIT();
            CP_WAIT1();
        } else {
            CP_WAIT0();
        }
        __syncthreads();

        const uint32_t bb = sb + (uint32_t)buf * STAGE_B;
        #pragma unroll
        for (int kc = 0; kc < 2; kc++) {
            // A frags: levels 1,2 for 2 m-tiles
            uint32_t a1[2][4], a2[2][4];
            {
                const uint32_t gr = (uint32_t)kc * 2 + ((lid >> 4) & 1);
                #pragma unroll
                for (int mi = 0; mi < 2; mi++) {
                    uint32_t row = oc0 + mi * 16 + (lid & 7) + ((lid >> 3) & 1) * 8;
                    uint32_t off = row * ROWP + gr * 16;
                    ldsm_x4(a1[mi], bb + OFF_A1 + off);
                    ldsm_x4(a2[mi], bb + OFF_A2 + off);
                }
            }
            // B: 2 pairs of n8 tiles
            const uint32_t bgr = (uint32_t)kc * 2 + ((lid >> 3) & 1);
            #pragma unroll
            for (int np = 0; np < 2; np++) {
                uint32_t col = n0 + np * 16 + ((lid >> 4) & 1) * 8 + (lid & 7);
                uint32_t boff = col * ROWP + bgr * 16;
                uint32_t b1[4], b2[4];
                ldsm_x4(b1, bb + OFF_B1 + boff);
                ldsm_x4(b2, bb + OFF_B2 + boff);
                const int ni = np * 2;
                // T1 = X1W1
                imma(d1[0][ni],     a1[0], b1 + 0);
                imma(d1[0][ni + 1], a1[0], b1 + 2);
                imma(d1[1][ni],     a1[1], b1 + 0);
                imma(d1[1][ni + 1], a1[1], b1 + 2);
                // T2 = X2W1
                imma(d2[0][ni],     a1[0], b2 + 0);
                imma(d2[0][ni + 1], a1[0], b2 + 2);
                imma(d2[1][ni],     a1[1], b2 + 0);
                imma(d2[1][ni + 1], a1[1], b2 + 2);
                // T2 += X1W2
                imma(d2[0][ni],     a2[0], b1 + 0);
                imma(d2[0][ni + 1], a2[0], b1 + 2);
                imma(d2[1][ni],     a2[1], b1 + 0);
                imma(d2[1][ni + 1], a2[1], b1 + 2);
            }
        }
        __syncthreads();
    }

    // ---- epilogue: scale + mish, transpose through smem, coalesced out ----
    float* ep = (float*)smem;        // [128 px][132]
    float fa[2][2];
    #pragma unroll
    for (int mi = 0; mi < 2; mi++) {
        fa[mi][0] = g_fs[b * COUT + oc0 + mi * 16 + (lid >> 2)];
        fa[mi][1] = g_fs[b * COUT + oc0 + mi * 16 + (lid >> 2) + 8];
    }
    #pragma unroll
    for (int mi = 0; mi < 2; mi++) {
        #pragma unroll
        for (int ni = 0; ni < 4; ni++) {
            #pragma unroll
            for (int j = 0; j < 4; j++) {
                int oc = oc0 + mi * 16 + (lid >> 2) + ((j >> 1) ? 8 : 0);
                int px = n0 + ni * 8 + (lid & 3) * 2 + (j & 1);
                float v = ((float)d1[mi][ni][j] + (float)d2[mi][ni][j] * 0.0078125f) * fa[mi][(j >> 1)];
                ep[px * 132 + oc] = mishf(v);
            }
        }
    }
    __syncthreads();

    const int oc2 = t & 127;
    const int qd  = t >> 7;          // quarter: 32 px
    float* dst = out + (((size_t)(b * COUT + oc2)) * HW + y0) * HW + qd * 32;
    #pragma unroll
    for (int g = 0; g < 8; g++) {
        int px = qd * 32 + g * 4;
        float4 v;
        v.x = ep[(px + 0) * 132 + oc2];
        v.y = ep[(px + 1) * 132 + oc2];
        v.z = ep[(px + 2) * 132 + oc2];
        v.w = ep[(px + 3) * 132 + oc2];
        *(float4*)(dst + g * 4) = v;
    }
}

// ---------------- launch ----------------
extern "C" void kernel_launch(void* const* d_in, const int* in_sizes, int n_in,
                              void* d_out, int out_size) {
    const float* x    = (const float*)d_in[0];
    const float* z    = (const float*)d_in[1];
    const float* w    = (const float*)d_in[2];
    const float* Wsty = (const float*)d_in[3];
    const float* bsty = (const float*)d_in[4];
    float* out = (float*)d_out;

    cudaFuncSetAttribute(conv_mma_kernel, cudaFuncAttributeMaxDynamicSharedMemorySize, SM_TOTAL);
    cudaFuncSetAttribute(xquant_kernel, cudaFuncAttributeMaxDynamicSharedMemorySize, 128 * 133 * 4);

    zmax_kernel<<<1, 32>>>();
    style_kernel<<<B_, CIN>>>(z, Wsty, bsty);
    ssum_kernel<<<COUT, CIN>>>(w);
    dscale_kernel<<<B_, COUT>>>();
    xmax_kernel<<<B_ * 8, 256>>>(x);
    wquant_kernel<<<B_ * COUT, CIN>>>(w);
    xquant_kernel<<<B_ * HW, 256, 128 * 133 * 4>>>(x);
    conv_mma_kernel<<<B_ * HW, 512, SM_TOTAL>>>(out);
}

// round 13
// speedup vs baseline: 5.0325x; 5.0325x over previous
#include <cuda_runtime.h>
#include <cuda_fp16.h>
#include <math.h>
#include <stdint.h>

#define B_      32
#define CIN     128
#define COUT    128
#define HW      128
#define ZD      512
#define EPSV    1e-8f

// ---------------- device scratch ----------------
__device__ float g_mod[B_ * CIN];
__device__ float g_S[COUT * CIN];
__device__ float g_dscale[B_ * COUT];
// weights fp16: [st = tap*2+ihalf][oc][64]
__device__ __align__(256) __half g_wh[18 * 128 * 64];
// x*mod fp16, NHWC: [b][y][x][ic]
__device__ __align__(256) __half g_xh[(size_t)B_ * HW * HW * CIN];

// ---------------- helpers ----------------
__device__ __forceinline__ uint32_t smem_u32(const void* p) {
    uint32_t a;
    asm("{ .reg .u64 t; cvta.to.shared.u64 t, %1; cvt.u32.u64 %0, t; }" : "=r"(a) : "l"(p));
    return a;
}
__device__ __forceinline__ void cpasync16(uint32_t dst, const void* src, int sz) {
    asm volatile("cp.async.cg.shared.global [%0], [%1], 16, %2;"
        :: "r"(dst), "l"(src), "r"(sz) : "memory");
}
#define CP_COMMIT() asm volatile("cp.async.commit_group;" ::: "memory")
#define CP_WAIT1()  asm volatile("cp.async.wait_group 1;" ::: "memory")
#define CP_WAIT0()  asm volatile("cp.async.wait_group 0;" ::: "memory")

__device__ __forceinline__ void ldsm_x4(uint32_t a[4], uint32_t addr) {
    asm volatile("ldmatrix.sync.aligned.m8n8.x4.shared.b16 {%0,%1,%2,%3}, [%4];"
        : "=r"(a[0]), "=r"(a[1]), "=r"(a[2]), "=r"(a[3]) : "r"(addr));
}
__device__ __forceinline__ void mma16816(float d[4], const uint32_t a[4], const uint32_t b[2]) {
    asm volatile("mma.sync.aligned.m16n8k16.row.col.f32.f16.f16.f32 "
        "{%0,%1,%2,%3}, {%4,%5,%6,%7}, {%8,%9}, {%0,%1,%2,%3};"
        : "+f"(d[0]), "+f"(d[1]), "+f"(d[2]), "+f"(d[3])
        : "r"(a[0]), "r"(a[1]), "r"(a[2]), "r"(a[3]), "r"(b[0]), "r"(b[1]));
}
__device__ __forceinline__ float mishf(float v) {
    return v * tanhf(log1pf(expf(v)));
}

// ---------------- pre-kernels ----------------
__global__ void style_kernel(const float* __restrict__ z,
                             const float* __restrict__ Wsty,
                             const float* __restrict__ bsty) {
    int b = blockIdx.x, i = threadIdx.x;
    __shared__ float zs[ZD];
    for (int k = threadIdx.x; k < ZD; k += blockDim.x) zs[k] = z[b * ZD + k];
    __syncthreads();
    float s = bsty[i];
    const float* wr = Wsty + i * ZD;
    #pragma unroll 4
    for (int k = 0; k < ZD; k++) s += zs[k] * wr[k];
    g_mod[b * CIN + i] = s + 1.0f;
}

__global__ void ssum_kernel(const float* __restrict__ w) {
    int o = blockIdx.x, i = threadIdx.x;
    const float* p = w + (o * CIN + i) * 9;
    float s = 0.f;
    #pragma unroll
    for (int k = 0; k < 9; k++) s += p[k] * p[k];
    g_S[o * CIN + i] = s;
}

__global__ void dscale_kernel() {
    int b = blockIdx.x, o = threadIdx.x;
    const float* m = g_mod + b * CIN;
    const float* s = g_S + o * CIN;
    float acc = 0.f;
    #pragma unroll 4
    for (int i = 0; i < CIN; i++) { float mv = m[i]; acc += mv * mv * s[i]; }
    g_dscale[b * COUT + o] = rsqrtf(acc + EPSV);
}

// weight -> fp16, A layout [st][oc][64]
__global__ void wcvt_kernel(const float* __restrict__ w) {
    int idx = blockIdx.x * 512 + threadIdx.x;      // 0..147455
    int j   = idx & 63;
    int oc  = (idx >> 6) & 127;
    int st  = idx >> 13;
    int ih  = st & 1;
    int tap = st >> 1;
    g_wh[idx] = __float2half_rn(w[(oc * CIN + (ih * 64 + j)) * 9 + tap]);
}

// x*mod -> fp16 NHWC. one block per (b,y), 256 threads.
__global__ void xcvt_kernel(const float* __restrict__ x) {
    extern __shared__ float sm[];   // 128 * 133
    int b = blockIdx.x >> 7;
    int y = blockIdx.x & 127;
    #pragma unroll
    for (int i = 0; i < 16; i++) {
        int idx4 = i * 256 + threadIdx.x;          // 0..4095
        int ic = idx4 >> 5;
        int x4 = (idx4 & 31) * 4;
        float4 v = *(const float4*)(x + (((size_t)(b * CIN + ic)) * HW + y) * HW + x4);
        float m = g_mod[b * CIN + ic];
        float* d = sm + ic * 133 + x4;
        d[0] = v.x * m; d[1] = v.y * m; d[2] = v.z * m; d[3] = v.w * m;
    }
    __syncthreads();
    int xc = threadIdx.x >> 1;
    int ih = threadIdx.x & 1;
    size_t o = (((size_t)(b * HW + y)) * HW + xc) * CIN + ih * 64;
    __half2* oh = (__half2*)(g_xh + o);
    #pragma unroll
    for (int q = 0; q < 32; q++) {
        float v0 = sm[(ih * 64 + 2 * q) * 133 + xc];
        float v1 = sm[(ih * 64 + 2 * q + 1) * 133 + xc];
        oh[q] = __floats2half2_rn(v0, v1);
    }
}

// ---------------- main conv: fp16 mma.sync implicit GEMM, 1 term ----------------
// CTA = (b, 2 image rows). D[128 oc x 256 px], K = 18 stages of 64.
// stage: A 16KB + B 32KB = 48KB; double buffered = 96KB. Epilogue 132KB.
#define STAGE_B  49152
#define OFF_A    0
#define OFF_B    16384
#define SM_TOTAL 135168
#define SWZ(row, cb) ((cb) ^ (((row) & 7) << 4))

__global__ void __launch_bounds__(256, 1)
conv_mma_kernel(float* __restrict__ out) {
    extern __shared__ __align__(1024) unsigned char smem[];
    const uint32_t sb = smem_u32(smem);
    const int t   = threadIdx.x;
    const int wid = t >> 5;
    const int lid = t & 31;
    const int b   = blockIdx.x >> 6;
    const int y0  = (blockIdx.x & 63) << 1;

    const int oc0 = (wid & 3) * 32;   // warp oc block (32)
    const int n0  = (wid >> 2) * 128; // warp px block (128)

    float d[2][16][4];
    #pragma unroll
    for (int mi = 0; mi < 2; mi++)
        #pragma unroll
        for (int ni = 0; ni < 16; ni++)
            #pragma unroll
            for (int j = 0; j < 4; j++) d[mi][ni][j] = 0.f;

    auto issue_stage = [&](int s, int buf) {
        const int tap = s >> 1;
        const int ih  = s & 1;
        const int ky  = tap / 3;
        const int kx  = tap - ky * 3;
        const uint32_t bb = sb + (uint32_t)buf * STAGE_B;
        // A: 1024 x 16B
        #pragma unroll
        for (int i = 0; i < 4; i++) {
            int idx = i * 256 + t;                 // 0..1023
            int oc  = idx >> 3, c = idx & 7;
            const __half* src = g_wh + (size_t)s * 8192 + oc * 64 + c * 8;
            cpasync16(bb + OFF_A + oc * 128 + SWZ(oc, c * 16), src, 16);
        }
        // B: 2048 x 16B (256 px), halo zfill
        #pragma unroll
        for (int i = 0; i < 8; i++) {
            int idx = i * 256 + t;                 // 0..2047
            int px  = idx >> 3, c = idx & 7;
            int yi  = y0 + (px >> 7) + ky - 1;
            int xi  = (px & 127) + kx - 1;
            bool ok = (unsigned)yi < (unsigned)HW && (unsigned)xi < (unsigned)HW;
            const __half* src = g_xh
                + (((size_t)(b * HW + (ok ? yi : 0))) * HW + (ok ? xi : 0)) * CIN + ih * 64 + c * 8;
            cpasync16(bb + OFF_B + px * 128 + SWZ(px, c * 16), src, ok ? 16 : 0);
        }
    };

    issue_stage(0, 0);
    CP_COMMIT();

    for (int s = 0; s < 18; s++) {
        const int buf = s & 1;
        if (s + 1 < 18) {
            issue_stage(s + 1, buf ^ 1);
            CP_COMMIT();
            CP_WAIT1();
        } else {
            CP_WAIT0();
        }
        __syncthreads();

        const uint32_t bb = sb + (uint32_t)buf * STAGE_B;
        #pragma unroll
        for (int k16 = 0; k16 < 4; k16++) {
            uint32_t a[2][4];
            {
                const uint32_t acb = (uint32_t)k16 * 32 + ((lid >> 4) & 1) * 16;
                #pragma unroll
                for (int mi = 0; mi < 2; mi++) {
                    uint32_t row = oc0 + mi * 16 + (lid & 7) + ((lid >> 3) & 1) * 8;
                    ldsm_x4(a[mi], bb + OFF_A + row * 128 + SWZ(row, acb));
                }
            }
            const uint32_t bcb = (uint32_t)k16 * 32 + ((lid >> 3) & 1) * 16;
            #pragma unroll
            for (int nj = 0; nj < 8; nj++) {
                uint32_t brow = n0 + nj * 16 + ((lid >> 4) & 1) * 8 + (lid & 7);
                uint32_t b4[4];
                ldsm_x4(b4, bb + OFF_B + brow * 128 + SWZ(brow, bcb));
                mma16816(d[0][2 * nj + 0], a[0], b4 + 0);
                mma16816(d[1][2 * nj + 0], a[1], b4 + 0);
                mma16816(d[0][2 * nj + 1], a[0], b4 + 2);
                mma16816(d[1][2 * nj + 1], a[1], b4 + 2);
            }
        }
        __syncthreads();
    }

    // ---- epilogue: dscale * mish, transpose through smem, coalesced out ----
    float* ep = (float*)smem;        // [256 px][132]
    float dsc[2][2];
    #pragma unroll
    for (int mi = 0; mi < 2; mi++) {
        dsc[mi][0] = g_dscale[b * COUT + oc0 + mi * 16 + (lid >> 2)];
        dsc[mi][1] = g_dscale[b * COUT + oc0 + mi * 16 + (lid >> 2) + 8];
    }
    #pragma unroll
    for (int mi = 0; mi < 2; mi++) {
        #pragma unroll
        for (int ni = 0; ni < 16; ni++) {
            #pragma unroll
            for (int j = 0; j < 4; j++) {
                int oc = oc0 + mi * 16 + (lid >> 2) + ((j >> 1) ? 8 : 0);
                int px = n0 + ni * 8 + (lid & 3) * 2 + (j & 1);
                ep[px * 132 + oc] = mishf(d[mi][ni][j] * dsc[mi][(j >> 1)]);
            }
        }
    }
    __syncthreads();

    const int oc2 = t & 127;
    const int r   = t >> 7;          // output row within tile
    float* dst = out + (((size_t)(b * COUT + oc2)) * HW + (y0 + r)) * HW;
    #pragma unroll
    for (int g = 0; g < 32; g++) {
        int px = r * 128 + g * 4;
        float4 v;
        v.x = ep[(px + 0) * 132 + oc2];
        v.y = ep[(px + 1) * 132 + oc2];
        v.z = ep[(px + 2) * 132 + oc2];
        v.w = ep[(px + 3) * 132 + oc2];
        *(float4*)(dst + g * 4) = v;
    }
}

// ---------------- launch ----------------
extern "C" void kernel_launch(void* const* d_in, const int* in_sizes, int n_in,
                              void* d_out, int out_size) {
    const float* x    = (const float*)d_in[0];
    const float* z    = (const float*)d_in[1];
    const float* w    = (const float*)d_in[2];
    const float* Wsty = (const float*)d_in[3];
    const float* bsty = (const float*)d_in[4];
    float* out = (float*)d_out;

    cudaFuncSetAttribute(conv_mma_kernel, cudaFuncAttributeMaxDynamicSharedMemorySize, SM_TOTAL);
    cudaFuncSetAttribute(xcvt_kernel, cudaFuncAttributeMaxDynamicSharedMemorySize, 128 * 133 * 4);

    style_kernel<<<B_, CIN>>>(z, Wsty, bsty);
    ssum_kernel<<<COUT, CIN>>>(w);
    dscale_kernel<<<B_, COUT>>>();
    wcvt_kernel<<<288, 512>>>(w);
    xcvt_kernel<<<B_ * HW, 256, 128 * 133 * 4>>>(x);
    conv_mma_kernel<<<B_ * 64, 256, SM_TOTAL>>>(out);
}

// round 14
// speedup vs baseline: 5.0534x; 1.0041x over previous
#include <cuda_runtime.h>
#include <cuda_fp16.h>
#include <math.h>
#include <stdint.h>

#define B_      32
#define CIN     128
#define COUT    128
#define HW      128
#define ZD      512
#define EPSV    1e-8f

// ---------------- device scratch ----------------
__device__ float g_mod[B_ * CIN];
__device__ float g_S[COUT * CIN];
__device__ float g_dscale[B_ * COUT];
// weights fp16: [st = tap*2+ihalf][oc][64]
__device__ __align__(256) __half g_wh[18 * 128 * 64];
// x*mod fp16, NHWC: [b][y][x][ic]
__device__ __align__(256) __half g_xh[(size_t)B_ * HW * HW * CIN];

// ---------------- helpers ----------------
__device__ __forceinline__ uint32_t smem_u32(const void* p) {
    uint32_t a;
    asm("{ .reg .u64 t; cvta.to.shared.u64 t, %1; cvt.u32.u64 %0, t; }" : "=r"(a) : "l"(p));
    return a;
}
__device__ __forceinline__ void cpasync16(uint32_t dst, const void* src, int sz) {
    asm volatile("cp.async.cg.shared.global [%0], [%1], 16, %2;"
        :: "r"(dst), "l"(src), "r"(sz) : "memory");
}
#define CP_COMMIT() asm volatile("cp.async.commit_group;" ::: "memory")
#define CP_WAIT1()  asm volatile("cp.async.wait_group 1;" ::: "memory")
#define CP_WAIT0()  asm volatile("cp.async.wait_group 0;" ::: "memory")

__device__ __forceinline__ void ldsm_x4(uint32_t a[4], uint32_t addr) {
    asm volatile("ldmatrix.sync.aligned.m8n8.x4.shared.b16 {%0,%1,%2,%3}, [%4];"
        : "=r"(a[0]), "=r"(a[1]), "=r"(a[2]), "=r"(a[3]) : "r"(addr));
}
__device__ __forceinline__ void mma16816(float d[4], const uint32_t a[4], const uint32_t b[2]) {
    asm volatile("mma.sync.aligned.m16n8k16.row.col.f32.f16.f16.f32 "
        "{%0,%1,%2,%3}, {%4,%5,%6,%7}, {%8,%9}, {%0,%1,%2,%3};"
        : "+f"(d[0]), "+f"(d[1]), "+f"(d[2]), "+f"(d[3])
        : "r"(a[0]), "r"(a[1]), "r"(a[2]), "r"(a[3]), "r"(b[0]), "r"(b[1]));
}
__device__ __forceinline__ float mishf(float v) {
    return v * tanhf(log1pf(expf(v)));
}

// ---------------- pre-kernels ----------------
__global__ void style_kernel(const float* __restrict__ z,
                             const float* __restrict__ Wsty,
                             const float* __restrict__ bsty) {
    int b = blockIdx.x, i = threadIdx.x;
    __shared__ float zs[ZD];
    for (int k = threadIdx.x; k < ZD; k += blockDim.x) zs[k] = z[b * ZD + k];
    __syncthreads();
    float s = bsty[i];
    const float* wr = Wsty + i * ZD;
    #pragma unroll 4
    for (int k = 0; k < ZD; k++) s += zs[k] * wr[k];
    g_mod[b * CIN + i] = s + 1.0f;
}

__global__ void ssum_kernel(const float* __restrict__ w) {
    int o = blockIdx.x, i = threadIdx.x;
    const float* p = w + (o * CIN + i) * 9;
    float s = 0.f;
    #pragma unroll
    for (int k = 0; k < 9; k++) s += p[k] * p[k];
    g_S[o * CIN + i] = s;
}

// warp per (b,o) pair; grid 512 x 256thr
__global__ void dscale_kernel() {
    int pair = blockIdx.x * 8 + (threadIdx.x >> 5);  // 0..4095
    int b = pair >> 7, o = pair & 127;
    int lane = threadIdx.x & 31;
    const float* m = g_mod + b * CIN;
    const float* s = g_S + o * CIN;
    float acc = 0.f;
    #pragma unroll
    for (int q = 0; q < 4; q++) {
        int i = q * 32 + lane;
        float mv = m[i];
        acc += mv * mv * s[i];
    }
    #pragma unroll
    for (int off = 16; off; off >>= 1) acc += __shfl_xor_sync(0xffffffffu, acc, off);
    if (lane == 0) g_dscale[pair] = rsqrtf(acc + EPSV);
}

// weight -> fp16, A layout [st][oc][64]
__global__ void wcvt_kernel(const float* __restrict__ w) {
    int idx = blockIdx.x * 512 + threadIdx.x;      // 0..147455
    int j   = idx & 63;
    int oc  = (idx >> 6) & 127;
    int st  = idx >> 13;
    int ih  = st & 1;
    int tap = st >> 1;
    g_wh[idx] = __float2half_rn(w[(oc * CIN + (ih * 64 + j)) * 9 + tap]);
}

// x*mod -> fp16 NHWC. one block per (b,y), 256 threads.
__global__ void xcvt_kernel(const float* __restrict__ x) {
    extern __shared__ float sm[];   // 128 * 133
    int b = blockIdx.x >> 7;
    int y = blockIdx.x & 127;
    #pragma unroll
    for (int i = 0; i < 16; i++) {
        int idx4 = i * 256 + threadIdx.x;          // 0..4095
        int ic = idx4 >> 5;
        int x4 = (idx4 & 31) * 4;
        float4 v = *(const float4*)(x + (((size_t)(b * CIN + ic)) * HW + y) * HW + x4);
        float m = g_mod[b * CIN + ic];
        float* d = sm + ic * 133 + x4;
        d[0] = v.x * m; d[1] = v.y * m; d[2] = v.z * m; d[3] = v.w * m;
    }
    __syncthreads();
    int xc = threadIdx.x >> 1;
    int ih = threadIdx.x & 1;
    size_t o = (((size_t)(b * HW + y)) * HW + xc) * CIN + ih * 64;
    __half2* oh = (__half2*)(g_xh + o);
    #pragma unroll
    for (int q = 0; q < 32; q++) {
        float v0 = sm[(ih * 64 + 2 * q) * 133 + xc];
        float v1 = sm[(ih * 64 + 2 * q + 1) * 133 + xc];
        oh[q] = __floats2half2_rn(v0, v1);
    }
}

// ---------------- main conv: fp16 mma.sync, 512 threads / 16 warps ----------------
// CTA = (b, 2 image rows). D[128 oc x 256 px], K = 18 stages of 64.
// warp tile: 32 oc x 64 px. stage: A 16KB + B 32KB; double buffered = 96KB.
#define STAGE_B  49152
#define OFF_A    0
#define OFF_B    16384
#define SM_TOTAL 135168
#define SWZ(row, cb) ((cb) ^ (((row) & 7) << 4))

__global__ void __launch_bounds__(512, 1)
conv_mma_kernel(float* __restrict__ out) {
    extern __shared__ __align__(1024) unsigned char smem[];
    const uint32_t sb = smem_u32(smem);
    const int t   = threadIdx.x;
    const int wid = t >> 5;
    const int lid = t & 31;
    const int b   = blockIdx.x >> 6;
    const int y0  = (blockIdx.x & 63) << 1;

    const int oc0 = (wid & 3) * 32;   // warp oc block (32)
    const int n0  = (wid >> 2) * 64;  // warp px block (64)

    float d[2][8][4];
    #pragma unroll
    for (int mi = 0; mi < 2; mi++)
        #pragma unroll
        for (int ni = 0; ni < 8; ni++)
            #pragma unroll
            for (int j = 0; j < 4; j++) d[mi][ni][j] = 0.f;

    auto issue_stage = [&](int s, int buf) {
        const int tap = s >> 1;
        const int ih  = s & 1;
        const int ky  = tap / 3;
        const int kx  = tap - ky * 3;
        const uint32_t bb = sb + (uint32_t)buf * STAGE_B;
        // A: 1024 x 16B
        #pragma unroll
        for (int i = 0; i < 2; i++) {
            int idx = i * 512 + t;                 // 0..1023
            int oc  = idx >> 3, c = idx & 7;
            const __half* src = g_wh + (size_t)s * 8192 + oc * 64 + c * 8;
            cpasync16(bb + OFF_A + oc * 128 + SWZ(oc, c * 16), src, 16);
        }
        // B: 2048 x 16B (256 px), halo zfill
        #pragma unroll
        for (int i = 0; i < 4; i++) {
            int idx = i * 512 + t;                 // 0..2047
            int px  = idx >> 3, c = idx & 7;
            int yi  = y0 + (px >> 7) + ky - 1;
            int xi  = (px & 127) + kx - 1;
            bool ok = (unsigned)yi < (unsigned)HW && (unsigned)xi < (unsigned)HW;
            const __half* src = g_xh
                + (((size_t)(b * HW + (ok ? yi : 0))) * HW + (ok ? xi : 0)) * CIN + ih * 64 + c * 8;
            cpasync16(bb + OFF_B + px * 128 + SWZ(px, c * 16), src, ok ? 16 : 0);
        }
    };

    issue_stage(0, 0);
    CP_COMMIT();

    for (int s = 0; s < 18; s++) {
        const int buf = s & 1;
        if (s + 1 < 18) {
            issue_stage(s + 1, buf ^ 1);
            CP_COMMIT();
            CP_WAIT1();
        } else {
            CP_WAIT0();
        }
        __syncthreads();

        const uint32_t bb = sb + (uint32_t)buf * STAGE_B;
        #pragma unroll
        for (int k16 = 0; k16 < 4; k16++) {
            uint32_t a[2][4];
            {
                const uint32_t acb = (uint32_t)k16 * 32 + ((lid >> 4) & 1) * 16;
                #pragma unroll
                for (int mi = 0; mi < 2; mi++) {
                    uint32_t row = oc0 + mi * 16 + (lid & 7) + ((lid >> 3) & 1) * 8;
                    ldsm_x4(a[mi], bb + OFF_A + row * 128 + SWZ(row, acb));
                }
            }
            const uint32_t bcb = (uint32_t)k16 * 32 + ((lid >> 3) & 1) * 16;
            #pragma unroll
            for (int nj = 0; nj < 4; nj++) {
                uint32_t brow = n0 + nj * 16 + ((lid >> 4) & 1) * 8 + (lid & 7);
                uint32_t b4[4];
                ldsm_x4(b4, bb + OFF_B + brow * 128 + SWZ(brow, bcb));
                mma16816(d[0][2 * nj + 0], a[0], b4 + 0);
                mma16816(d[1][2 * nj + 0], a[1], b4 + 0);
                mma16816(d[0][2 * nj + 1], a[0], b4 + 2);
                mma16816(d[1][2 * nj + 1], a[1], b4 + 2);
            }
        }
        __syncthreads();
    }

    // ---- epilogue: dscale * mish, transpose through smem, coalesced out ----
    float* ep = (float*)smem;        // [256 px][132]
    float dsc[2][2];
    #pragma unroll
    for (int mi = 0; mi < 2; mi++) {
        dsc[mi][0] = g_dscale[b * COUT + oc0 + mi * 16 + (lid >> 2)];
        dsc[mi][1] = g_dscale[b * COUT + oc0 + mi * 16 + (lid >> 2) + 8];
    }
    #pragma unroll
    for (int mi = 0; mi < 2; mi++) {
        #pragma unroll
        for (int ni = 0; ni < 8; ni++) {
            #pragma unroll
            for (int j = 0; j < 4; j++) {
                int oc = oc0 + mi * 16 + (lid >> 2) + ((j >> 1) ? 8 : 0);
                int px = n0 + ni * 8 + (lid & 3) * 2 + (j & 1);
                ep[px * 132 + oc] = mishf(d[mi][ni][j] * dsc[mi][(j >> 1)]);
            }
        }
    }
    __syncthreads();

    // 512 threads: oc2 = t&127, slot = t>>7 (0..3) -> row r = slot>>1, half h = slot&1
    const int oc2  = t & 127;
    const int slot = t >> 7;
    const int r    = slot >> 1;
    const int h    = slot & 1;
    float* dst = out + (((size_t)(b * COUT + oc2)) * HW + (y0 + r)) * HW + h * 64;
    #pragma unroll
    for (int g = 0; g < 16; g++) {
        int px = r * 128 + h * 64 + g * 4;
        float4 v;
        v.x = ep[(px + 0) * 132 + oc2];
        v.y = ep[(px + 1) * 132 + oc2];
        v.z = ep[(px + 2) * 132 + oc2];
        v.w = ep[(px + 3) * 132 + oc2];
        *(float4*)(dst + g * 4) = v;
    }
}

// ---------------- launch ----------------
extern "C" void kernel_launch(void* const* d_in, const int* in_sizes, int n_in,
                              void* d_out, int out_size) {
    const float* x    = (const float*)d_in[0];
    const float* z    = (const float*)d_in[1];
    const float* w    = (const float*)d_in[2];
    const float* Wsty = (const float*)d_in[3];
    const float* bsty = (const float*)d_in[4];
    float* out = (float*)d_out;

    cudaFuncSetAttribute(conv_mma_kernel, cudaFuncAttributeMaxDynamicSharedMemorySize, SM_TOTAL);
    cudaFuncSetAttribute(xcvt_kernel, cudaFuncAttributeMaxDynamicSharedMemorySize, 128 * 133 * 4);

    style_kernel<<<B_, CIN>>>(z, Wsty, bsty);
    ssum_kernel<<<COUT, CIN>>>(w);
    dscale_kernel<<<512, 256>>>();
    wcvt_kernel<<<288, 512>>>(w);
    xcvt_kernel<<<B_ * HW, 256, 128 * 133 * 4>>>(x);
    conv_mma_kernel<<<B_ * 64, 512, SM_TOTAL>>>(out);
}